// round 9
// baseline (speedup 1.0000x reference)
#include <cuda_runtime.h>
#include <cstdint>

#define T_STEPS 2048
#define BATCH   256
#define HDIM    200
#define IN_DIM  27
#define NCLS    2

#define NGROUPS  16     // batch tiles; groups are mutually independent
#define GSIZE    8      // hd tiles per group -> 8-CTA barrier groups
#define GRID_CTAS (NGROUPS * GSIZE)   // 128 CTAs, 1/SM (SMEM-limited)
#define TB 16     // batches per CTA
#define TH 25     // hidden units per CTA
#define ROWS 100  // 4 gates * TH
#define ROWS_PAD 128
#define NTHREADS 512    // R9: 16 warps for latency hiding (was 256)

// SMEM strides (floats): 16B-aligned rows, conflict-free quad-banks for LDS.128
#define WHH_S 212   // 53 quads/row, 53%8=5 -> 8 rows hit 8 distinct quad-banks
#define WIH_S 36    // 9 quads,  9%8=1
#define HS_S  204   // 51 quads, 51%8=3 -> rows bb..bb+3 distinct
#define XS_S  36
#define GS_S  17

struct SmemLayout {
    float whh[ROWS_PAD][WHH_S];   // 108544 B
    float wih[ROWS_PAD][WIH_S];   //  18432 B
    float hs[TB][HS_S];           //  13056 B (h staging, full HDIM per batch)
    float xs[2][TB][XS_S];        //   4608 B (double-buffered x)
    float bias[ROWS_PAD];         //    512 B
    float gates[ROWS_PAD][GS_S];  //   8704 B
    float c[TB][TH + 1];          //   1664 B
};
// total 155520 B -> 1 CTA/SM; 128 CTAs <= 148 SMs -> all co-resident.

__device__ float g_h[2][BATCH][HDIM];          // double-buffered h exchange (L2)
__device__ unsigned g_cnt[NGROUPS * 64];       // per-group arrive counters, 256B apart
__device__ unsigned g_ep [NGROUPS * 64];       // per-group epochs, 256B apart

typedef unsigned long long u64;

__device__ __forceinline__ void ffma2(u64& d, u64 a, u64 b) {
    asm("fma.rn.f32x2 %0, %1, %2, %3;" : "=l"(d) : "l"(a), "l"(b), "l"(d));
}
__device__ __forceinline__ float f2sum(u64 v) {
    return __uint_as_float((unsigned)v) + __uint_as_float((unsigned)(v >> 32));
}
__device__ __forceinline__ float sigf(float x) {
    float e = __expf(-x);
    return __fdividef(1.0f, 1.0f + e);
}
__device__ __forceinline__ float tanh_fast(float x) {
    float e = __expf(-2.0f * x);
    return __fdividef(2.0f, 1.0f + e) - 1.0f;
}
__device__ __forceinline__ unsigned ld_acq(const unsigned* p) {
    unsigned v;
    asm volatile("ld.acquire.gpu.u32 %0, [%1];" : "=r"(v) : "l"(p) : "memory");
    return v;
}
__device__ __forceinline__ unsigned atom_add_acqrel(unsigned* p, unsigned v) {
    unsigned o;
    asm volatile("atom.add.acq_rel.gpu.u32 %0, [%1], %2;"
                 : "=r"(o) : "l"(p), "r"(v) : "memory");
    return o;
}

__global__ void __launch_bounds__(NTHREADS, 1)
lstm_persistent(const float* __restrict__ x,      // [B][T][27]
                const float* __restrict__ W_ih,   // [800][27]
                const float* __restrict__ W_hh,   // [800][200]
                const float* __restrict__ b_ih,   // [800]
                const float* __restrict__ b_hh,   // [800]
                const float* __restrict__ fc_w,   // [2][200]
                const float* __restrict__ fc_b,   // [2]
                float* __restrict__ out, int out_size)
{
    extern __shared__ float smem_f[];
    SmemLayout& s = *reinterpret_cast<SmemLayout*>(smem_f);

    const int tid = threadIdx.x;
    const int bt  = blockIdx.x >> 3;   // group id (batch tile)
    const int ht  = blockIdx.x & 7;    // hd tile within group
    const int b0  = bt * TB;
    const int hd0 = ht * TH;

    unsigned* cnt = &g_cnt[bt * 64];
    unsigned* ep  = &g_ep [bt * 64];

    // ---- one-time staging: weight slices (row r = gate*25 + hl), bias, c=0 ----
    for (int i = tid; i < ROWS_PAD * HDIM; i += NTHREADS) {
        int r = i / HDIM, k = i - r * HDIM;
        float v = 0.0f;
        if (r < ROWS) {
            int gate = r / TH, hl = r - gate * TH;
            v = W_hh[(gate * HDIM + hd0 + hl) * HDIM + k];
        }
        s.whh[r][k] = v;
    }
    for (int i = tid; i < ROWS_PAD * 28; i += NTHREADS) {
        int r = i / 28, k = i - r * 28;
        float v = 0.0f;
        if (r < ROWS && k < IN_DIM) {
            int gate = r / TH, hl = r - gate * TH;
            v = W_ih[(gate * HDIM + hd0 + hl) * IN_DIM + k];
        }
        s.wih[r][k] = v;
    }
    if (tid < ROWS_PAD) {
        float v = 0.0f;
        if (tid < ROWS) {
            int gate = tid / TH, hl = tid - gate * TH;
            int gr = gate * HDIM + hd0 + hl;
            v = b_ih[gr] + b_hh[gr];
        }
        s.bias[tid] = v;
    }
    if (tid < TB * TH)                              // 400 items, 512 threads
        s.c[tid / TH][tid % TH] = 0.0f;
    for (int i = tid; i < TB * 28; i += NTHREADS) { // xs[0] for t=0
        int bl = i / 28, k = i - bl * 28;
        s.xs[0][bl][k] = (k < IN_DIM)
            ? x[((size_t)(b0 + bl) * T_STEPS + 0) * IN_DIM + k] : 0.0f;
    }

    // Barrier bookkeeping: read epoch BEFORE first arrive (no flip can precede
    // all 8 group arrivals, so this is race-free; relative compare -> replay-safe).
    unsigned seen = 0;
    if (tid == 0) seen = ld_acq(ep);
    __syncthreads();

    // R9 thread tile: ONE row (jb = tid>>2, 0..127) x 4 batches (bb+4i).
    const int jb = tid >> 2;
    const int bb = tid & 3;

    u64 a0, a1, a2, a3;   // packed accumulators for batches bb, bb+4, bb+8, bb+12

    // x-part of the gate pre-activations for buffer `buf` (resets accumulators)
    auto do_xpart = [&](int buf) {
        a0 = a1 = a2 = a3 = 0ull;
        #pragma unroll
        for (int kq = 0; kq < 7; ++kq) {
            ulonglong2 W  = *reinterpret_cast<const ulonglong2*>(&s.wih[jb][4 * kq]);
            ulonglong2 V0 = *reinterpret_cast<const ulonglong2*>(&s.xs[buf][bb][4 * kq]);
            ulonglong2 V1 = *reinterpret_cast<const ulonglong2*>(&s.xs[buf][bb + 4][4 * kq]);
            ulonglong2 V2 = *reinterpret_cast<const ulonglong2*>(&s.xs[buf][bb + 8][4 * kq]);
            ulonglong2 V3 = *reinterpret_cast<const ulonglong2*>(&s.xs[buf][bb + 12][4 * kq]);
            ffma2(a0, V0.x, W.x); ffma2(a0, V0.y, W.y);
            ffma2(a1, V1.x, W.x); ffma2(a1, V1.y, W.y);
            ffma2(a2, V2.x, W.x); ffma2(a2, V2.y, W.y);
            ffma2(a3, V3.x, W.x); ffma2(a3, V3.y, W.y);
        }
    };

    do_xpart(0);   // x-part for t=0 (xs[0] staged above, synced)

    for (int t = 0; t < T_STEPS; ++t) {
        if (t > 0) {
            // ---- wait for peers' h(t-1), then stage it from L2 ----
            if (tid == 0) {
                unsigned v;
                do { v = ld_acq(ep); } while (v == seen);
                seen = v;
            }
            __syncthreads();   // tid0's acquire ordered before everyone's reads
            {
                const float4* hsrc =
                    reinterpret_cast<const float4*>(&g_h[t & 1][b0][0]);
                for (int i = tid; i < TB * (HDIM / 4); i += NTHREADS) {
                    int bl = i / 50, kq = i - bl * 50;
                    float4 v = __ldcg(hsrc + i);       // L2, never stale L1
                    *reinterpret_cast<float4*>(&s.hs[bl][kq * 4]) = v;
                }
            }
            __syncthreads();

            // ---- recurrent GEMM: 50 k-quads over 200 cols ----
            #pragma unroll 10
            for (int kq = 0; kq < HDIM / 4; ++kq) {
                ulonglong2 W  = *reinterpret_cast<const ulonglong2*>(&s.whh[jb][4 * kq]);
                ulonglong2 V0 = *reinterpret_cast<const ulonglong2*>(&s.hs[bb][4 * kq]);
                ulonglong2 V1 = *reinterpret_cast<const ulonglong2*>(&s.hs[bb + 4][4 * kq]);
                ulonglong2 V2 = *reinterpret_cast<const ulonglong2*>(&s.hs[bb + 8][4 * kq]);
                ulonglong2 V3 = *reinterpret_cast<const ulonglong2*>(&s.hs[bb + 12][4 * kq]);
                ffma2(a0, V0.x, W.x); ffma2(a0, V0.y, W.y);
                ffma2(a1, V1.x, W.x); ffma2(a1, V1.y, W.y);
                ffma2(a2, V2.x, W.x); ffma2(a2, V2.y, W.y);
                ffma2(a3, V3.x, W.x); ffma2(a3, V3.y, W.y);
            }
        }

        // ---- scatter gate pre-activations (bias folded in) ----
        {
            float bs = s.bias[jb];
            s.gates[jb][bb]      = f2sum(a0) + bs;
            s.gates[jb][bb + 4]  = f2sum(a1) + bs;
            s.gates[jb][bb + 8]  = f2sum(a2) + bs;
            s.gates[jb][bb + 12] = f2sum(a3) + bs;
        }
        __syncthreads();

        // ---- cell update: 400 (b, hl) items; h -> L2 via stcg ----
        const int nxt = (t + 1) & 1;
        if (tid < TB * TH) {                      // 512 threads cover 400 items
            int b = tid / TH, hl = tid - (tid / TH) * TH;
            float gi = sigf(s.gates[hl][b]);
            float gf = sigf(s.gates[TH + hl][b]);
            float gg = tanh_fast(s.gates[2 * TH + hl][b]);
            float go = sigf(s.gates[3 * TH + hl][b]);
            float c = gf * s.c[b][hl] + gi * gg;
            s.c[b][hl] = c;
            __stcg(&g_h[nxt][b0 + b][hd0 + hl], go * tanh_fast(c));
        }

        // ---- arrive (release): bar.sync orders all threads' stcg before it ----
        __syncthreads();
        if (tid == 0) {
            unsigned old = atom_add_acqrel(cnt, 1u);
            if (old == GSIZE - 1) {
                atomicExch(cnt, 0u);          // ordered before flip by release below
                atom_add_acqrel(ep, 1u);      // flip
            }
        }

        // ---- hidden under peer skew: stage x(t+1) and compute its x-part ----
        if (t + 1 < T_STEPS) {
            for (int i = tid; i < TB * 28; i += NTHREADS) {
                int bl = i / 28, k = i - bl * 28;
                s.xs[nxt][bl][k] = (k < IN_DIM)
                    ? x[((size_t)(b0 + bl) * T_STEPS + (t + 1)) * IN_DIM + k] : 0.0f;
            }
            __syncthreads();
            do_xpart(nxt);
        }
    }

    // ---- final wait: peers' h(2047) (stored in g_h[0]) visible ----
    if (tid == 0) {
        unsigned v;
        do { v = ld_acq(ep); } while (v == seen);
        seen = v;
    }
    __syncthreads();
    {
        const float4* hsrc = reinterpret_cast<const float4*>(&g_h[0][b0][0]);
        for (int i = tid; i < TB * (HDIM / 4); i += NTHREADS) {
            int bl = i / 50, kq = i - bl * 50;
            float4 v = __ldcg(hsrc + i);
            *reinterpret_cast<float4*>(&s.hs[bl][kq * 4]) = v;
        }
    }
    __syncthreads();

    // outputs: [out(512) | h(51200) | c(51200)]
    if (ht == 0 && out_size >= NCLS * BATCH) {
        for (int i = tid; i < TB * NCLS; i += NTHREADS) {
            int bl = i >> 1, cls = i & 1;
            float acc = fc_b[cls];
            #pragma unroll 4
            for (int k = 0; k < HDIM; ++k)
                acc += s.hs[bl][k] * fc_w[cls * HDIM + k];
            out[(b0 + bl) * NCLS + cls] = sigf(acc);
        }
    }
    if (ht == 0 && out_size >= NCLS * BATCH + BATCH * HDIM) {
        for (int i = tid; i < TB * HDIM; i += NTHREADS) {
            int bl = i / HDIM, k = i - bl * HDIM;
            out[NCLS * BATCH + (size_t)(b0 + bl) * HDIM + k] = s.hs[bl][k];
        }
    }
    if (out_size >= NCLS * BATCH + 2 * BATCH * HDIM) {
        if (tid < TB * TH) {
            int b = tid / TH, hl = tid - (tid / TH) * TH;
            out[NCLS * BATCH + BATCH * HDIM + (size_t)(b0 + b) * HDIM + hd0 + hl]
                = s.c[b][hl];
        }
    }
}

extern "C" void kernel_launch(void* const* d_in, const int* in_sizes, int n_in,
                              void* d_out, int out_size) {
    const float* x     = (const float*)d_in[0];
    // d_in[1]=X_lengths (unused), d_in[2]=h0, d_in[3]=c0 (zeros, ignored)
    const float* W_ih  = (const float*)d_in[4];
    const float* W_hh  = (const float*)d_in[5];
    const float* b_ih  = (const float*)d_in[6];
    const float* b_hh  = (const float*)d_in[7];
    const float* fc_w  = (const float*)d_in[8];
    const float* fc_b  = (const float*)d_in[9];

    int smem = (int)sizeof(SmemLayout);
    cudaFuncSetAttribute(lstm_persistent,
                         cudaFuncAttributeMaxDynamicSharedMemorySize, smem);
    lstm_persistent<<<GRID_CTAS, NTHREADS, smem>>>(
        x, W_ih, W_hh, b_ih, b_hh, fc_w, fc_b, (float*)d_out, out_size);
}

// round 10
// speedup vs baseline: 1.4548x; 1.4548x over previous
#include <cuda_runtime.h>
#include <cstdint>

#define T_STEPS 2048
#define BATCH   256
#define HDIM    200
#define IN_DIM  27
#define NCLS    2

#define NGROUPS  16     // batch tiles; groups are mutually independent
#define GSIZE    8      // hd tiles per group -> 8-CTA barrier groups
#define GRID_CTAS (NGROUPS * GSIZE)   // 128 CTAs, 1/SM (SMEM-limited)
#define TB 16     // batches per CTA
#define TH 25     // hidden units per CTA
#define ROWS 100  // 4 gates * TH
#define ROWS_PAD 128
#define NTHREADS 512    // 16 warps; K split in 2 -> R8 tile shape per thread
#define KQ_HALF  25     // 25 k-quads (=100 cols) per K-slice

// SMEM strides (floats): 16B-aligned rows, conflict-free quad-banks for LDS.128
#define WHH_S 212   // 53 quads/row, 53%8=5 -> 8 rows hit 8 distinct quad-banks
#define WIH_S 36    // 9 quads,  9%8=1
#define HS_S  204   // 51 quads, 51%8=3
#define XS_S  36
#define GS_S  17
#define RED_S 9     // stride 9 (odd) -> conflict-free partial exchange

struct SmemLayout {
    float whh[ROWS_PAD][WHH_S];   // 108544 B
    float wih[ROWS_PAD][WIH_S];   //  18432 B
    float hs[TB][HS_S];           //  13056 B (h staging, full HDIM per batch)
    float xs[2][TB][XS_S];        //   4608 B (double-buffered x)
    float bias[ROWS_PAD];         //    512 B
    float gates[ROWS_PAD][GS_S];  //   8704 B
    float c[TB][TH + 1];          //   1664 B
    float red[256][RED_S];        //   9216 B (K-split partial sums)
};
// total 164736 B -> 1 CTA/SM; 128 CTAs <= 148 SMs -> all co-resident.

__device__ float g_h[2][BATCH][HDIM];          // double-buffered h exchange (L2)
__device__ unsigned g_cnt[NGROUPS * 64];       // per-group arrive counters, 256B apart
__device__ unsigned g_ep [NGROUPS * 64];       // per-group epochs, 256B apart

typedef unsigned long long u64;

__device__ __forceinline__ void ffma2(u64& d, u64 a, u64 b) {
    asm("fma.rn.f32x2 %0, %1, %2, %3;" : "=l"(d) : "l"(a), "l"(b), "l"(d));
}
__device__ __forceinline__ float f2sum(u64 v) {
    return __uint_as_float((unsigned)v) + __uint_as_float((unsigned)(v >> 32));
}
__device__ __forceinline__ float sigf(float x) {
    float e = __expf(-x);
    return __fdividef(1.0f, 1.0f + e);
}
__device__ __forceinline__ float tanh_fast(float x) {
    float e = __expf(-2.0f * x);
    return __fdividef(2.0f, 1.0f + e) - 1.0f;
}
__device__ __forceinline__ unsigned ld_acq(const unsigned* p) {
    unsigned v;
    asm volatile("ld.acquire.gpu.u32 %0, [%1];" : "=r"(v) : "l"(p) : "memory");
    return v;
}
__device__ __forceinline__ unsigned atom_add_acqrel(unsigned* p, unsigned v) {
    unsigned o;
    asm volatile("atom.add.acq_rel.gpu.u32 %0, [%1], %2;"
                 : "=r"(o) : "l"(p), "r"(v) : "memory");
    return o;
}

__global__ void __launch_bounds__(NTHREADS, 1)
lstm_persistent(const float* __restrict__ x,      // [B][T][27]
                const float* __restrict__ W_ih,   // [800][27]
                const float* __restrict__ W_hh,   // [800][200]
                const float* __restrict__ b_ih,   // [800]
                const float* __restrict__ b_hh,   // [800]
                const float* __restrict__ fc_w,   // [2][200]
                const float* __restrict__ fc_b,   // [2]
                float* __restrict__ out, int out_size)
{
    extern __shared__ float smem_f[];
    SmemLayout& s = *reinterpret_cast<SmemLayout*>(smem_f);

    const int tid = threadIdx.x;
    const int bt  = blockIdx.x >> 3;   // group id (batch tile)
    const int ht  = blockIdx.x & 7;    // hd tile within group
    const int b0  = bt * TB;
    const int hd0 = ht * TH;

    unsigned* cnt = &g_cnt[bt * 64];
    unsigned* ep  = &g_ep [bt * 64];

    // ---- one-time staging: weight slices (row r = gate*25 + hl), bias, c=0 ----
    for (int i = tid; i < ROWS_PAD * HDIM; i += NTHREADS) {
        int r = i / HDIM, k = i - r * HDIM;
        float v = 0.0f;
        if (r < ROWS) {
            int gate = r / TH, hl = r - gate * TH;
            v = W_hh[(gate * HDIM + hd0 + hl) * HDIM + k];
        }
        s.whh[r][k] = v;
    }
    for (int i = tid; i < ROWS_PAD * 28; i += NTHREADS) {
        int r = i / 28, k = i - r * 28;
        float v = 0.0f;
        if (r < ROWS && k < IN_DIM) {
            int gate = r / TH, hl = r - gate * TH;
            v = W_ih[(gate * HDIM + hd0 + hl) * IN_DIM + k];
        }
        s.wih[r][k] = v;
    }
    if (tid < ROWS_PAD) {
        float v = 0.0f;
        if (tid < ROWS) {
            int gate = tid / TH, hl = tid - gate * TH;
            int gr = gate * HDIM + hd0 + hl;
            v = b_ih[gr] + b_hh[gr];
        }
        s.bias[tid] = v;
    }
    if (tid < TB * TH)                              // 400 items, 512 threads
        s.c[tid / TH][tid % TH] = 0.0f;
    for (int i = tid; i < TB * 28; i += NTHREADS) { // xs[0] for t=0
        int bl = i / 28, k = i - bl * 28;
        s.xs[0][bl][k] = (k < IN_DIM)
            ? x[((size_t)(b0 + bl) * T_STEPS + 0) * IN_DIM + k] : 0.0f;
    }

    // Barrier bookkeeping: read epoch BEFORE first arrive (race-free; relative
    // compare -> replay/wrap safe).
    unsigned seen = 0;
    if (tid == 0) seen = ld_acq(ep);
    __syncthreads();

    // K-split thread tile: ks = K-half; within half: rows (jb, jb+64) x 4 batches
    const int ks = tid >> 8;          // 0: k in [0,100); 1: k in [100,200)
    const int p  = tid & 255;
    const int jb = p >> 2;            // 0..63
    const int bb = p & 3;
    const int r0 = jb;
    const int r1 = jb + 64;
    const int kq0 = ks * KQ_HALF;     // quad offset of this K-slice

    u64 a00, a01, a10, a11, a20, a21, a30, a31;

    // x-part (IN_DIM=27) computed by kslice 0 only; kslice 1 starts at zero.
    auto do_xpart = [&](int buf) {
        a00 = a01 = a10 = a11 = a20 = a21 = a30 = a31 = 0ull;
        if (ks == 0) {
            #pragma unroll
            for (int kq = 0; kq < 7; ++kq) {
                ulonglong2 W0 = *reinterpret_cast<const ulonglong2*>(&s.wih[r0][4 * kq]);
                ulonglong2 W1 = *reinterpret_cast<const ulonglong2*>(&s.wih[r1][4 * kq]);
                ulonglong2 V0 = *reinterpret_cast<const ulonglong2*>(&s.xs[buf][bb][4 * kq]);
                ulonglong2 V1 = *reinterpret_cast<const ulonglong2*>(&s.xs[buf][bb + 4][4 * kq]);
                ulonglong2 V2 = *reinterpret_cast<const ulonglong2*>(&s.xs[buf][bb + 8][4 * kq]);
                ulonglong2 V3 = *reinterpret_cast<const ulonglong2*>(&s.xs[buf][bb + 12][4 * kq]);
                ffma2(a00, V0.x, W0.x); ffma2(a00, V0.y, W0.y);
                ffma2(a01, V0.x, W1.x); ffma2(a01, V0.y, W1.y);
                ffma2(a10, V1.x, W0.x); ffma2(a10, V1.y, W0.y);
                ffma2(a11, V1.x, W1.x); ffma2(a11, V1.y, W1.y);
                ffma2(a20, V2.x, W0.x); ffma2(a20, V2.y, W0.y);
                ffma2(a21, V2.x, W1.x); ffma2(a21, V2.y, W1.y);
                ffma2(a30, V3.x, W0.x); ffma2(a30, V3.y, W0.y);
                ffma2(a31, V3.x, W1.x); ffma2(a31, V3.y, W1.y);
            }
        }
    };

    do_xpart(0);   // x-part for t=0 (xs[0] staged above, synced)

    for (int t = 0; t < T_STEPS; ++t) {
        if (t > 0) {
            // ---- wait for peers' h(t-1), then stage it from L2 ----
            if (tid == 0) {
                unsigned v;
                do { v = ld_acq(ep); } while (v == seen);
                seen = v;
            }
            __syncthreads();   // tid0's acquire ordered before everyone's reads
            {
                const float4* hsrc =
                    reinterpret_cast<const float4*>(&g_h[t & 1][b0][0]);
                for (int i = tid; i < TB * (HDIM / 4); i += NTHREADS) {
                    int bl = i / 50, kq = i - bl * 50;
                    float4 v = __ldcg(hsrc + i);       // L2, never stale L1
                    *reinterpret_cast<float4*>(&s.hs[bl][kq * 4]) = v;
                }
            }
            __syncthreads();

            // ---- recurrent GEMM: 25 k-quads (this K-slice) over 2x4 tile ----
            #pragma unroll 5
            for (int kq = 0; kq < KQ_HALF; ++kq) {
                int q = kq0 + kq;
                ulonglong2 W0 = *reinterpret_cast<const ulonglong2*>(&s.whh[r0][4 * q]);
                ulonglong2 W1 = *reinterpret_cast<const ulonglong2*>(&s.whh[r1][4 * q]);
                ulonglong2 V0 = *reinterpret_cast<const ulonglong2*>(&s.hs[bb][4 * q]);
                ulonglong2 V1 = *reinterpret_cast<const ulonglong2*>(&s.hs[bb + 4][4 * q]);
                ulonglong2 V2 = *reinterpret_cast<const ulonglong2*>(&s.hs[bb + 8][4 * q]);
                ulonglong2 V3 = *reinterpret_cast<const ulonglong2*>(&s.hs[bb + 12][4 * q]);
                ffma2(a00, V0.x, W0.x); ffma2(a00, V0.y, W0.y);
                ffma2(a01, V0.x, W1.x); ffma2(a01, V0.y, W1.y);
                ffma2(a10, V1.x, W0.x); ffma2(a10, V1.y, W0.y);
                ffma2(a11, V1.x, W1.x); ffma2(a11, V1.y, W1.y);
                ffma2(a20, V2.x, W0.x); ffma2(a20, V2.y, W0.y);
                ffma2(a21, V2.x, W1.x); ffma2(a21, V2.y, W1.y);
                ffma2(a30, V3.x, W0.x); ffma2(a30, V3.y, W0.y);
                ffma2(a31, V3.x, W1.x); ffma2(a31, V3.y, W1.y);
            }
        }

        // ---- K-split reduction + gate scatter (bias folded in) ----
        if (ks == 1) {
            s.red[p][0] = f2sum(a00);
            s.red[p][1] = f2sum(a01);
            s.red[p][2] = f2sum(a10);
            s.red[p][3] = f2sum(a11);
            s.red[p][4] = f2sum(a20);
            s.red[p][5] = f2sum(a21);
            s.red[p][6] = f2sum(a30);
            s.red[p][7] = f2sum(a31);
        }
        __syncthreads();
        if (ks == 0) {
            float bs0 = s.bias[r0], bs1 = s.bias[r1];
            s.gates[r0][bb]      = f2sum(a00) + s.red[p][0] + bs0;
            s.gates[r1][bb]      = f2sum(a01) + s.red[p][1] + bs1;
            s.gates[r0][bb + 4]  = f2sum(a10) + s.red[p][2] + bs0;
            s.gates[r1][bb + 4]  = f2sum(a11) + s.red[p][3] + bs1;
            s.gates[r0][bb + 8]  = f2sum(a20) + s.red[p][4] + bs0;
            s.gates[r1][bb + 8]  = f2sum(a21) + s.red[p][5] + bs1;
            s.gates[r0][bb + 12] = f2sum(a30) + s.red[p][6] + bs0;
            s.gates[r1][bb + 12] = f2sum(a31) + s.red[p][7] + bs1;
        }
        __syncthreads();

        // ---- cell update: 400 (b, hl) items; h -> L2 via stcg ----
        const int nxt = (t + 1) & 1;
        if (tid < TB * TH) {                      // 512 threads cover 400 items
            int b = tid / TH, hl = tid - (tid / TH) * TH;
            float gi = sigf(s.gates[hl][b]);
            float gf = sigf(s.gates[TH + hl][b]);
            float gg = tanh_fast(s.gates[2 * TH + hl][b]);
            float go = sigf(s.gates[3 * TH + hl][b]);
            float c = gf * s.c[b][hl] + gi * gg;
            s.c[b][hl] = c;
            __stcg(&g_h[nxt][b0 + b][hd0 + hl], go * tanh_fast(c));
        }

        // ---- arrive (release): bar.sync orders all threads' stcg before it ----
        __syncthreads();
        if (tid == 0) {
            unsigned old = atom_add_acqrel(cnt, 1u);
            if (old == GSIZE - 1) {
                atomicExch(cnt, 0u);          // ordered before flip by release below
                atom_add_acqrel(ep, 1u);      // flip
            }
        }

        // ---- hidden under peer skew: stage x(t+1) and compute its x-part ----
        if (t + 1 < T_STEPS) {
            for (int i = tid; i < TB * 28; i += NTHREADS) {
                int bl = i / 28, k = i - bl * 28;
                s.xs[nxt][bl][k] = (k < IN_DIM)
                    ? x[((size_t)(b0 + bl) * T_STEPS + (t + 1)) * IN_DIM + k] : 0.0f;
            }
            __syncthreads();
            do_xpart(nxt);
        }
    }

    // ---- final wait: peers' h(2047) (stored in g_h[0]) visible ----
    if (tid == 0) {
        unsigned v;
        do { v = ld_acq(ep); } while (v == seen);
        seen = v;
    }
    __syncthreads();
    {
        const float4* hsrc = reinterpret_cast<const float4*>(&g_h[0][b0][0]);
        for (int i = tid; i < TB * (HDIM / 4); i += NTHREADS) {
            int bl = i / 50, kq = i - bl * 50;
            float4 v = __ldcg(hsrc + i);
            *reinterpret_cast<float4*>(&s.hs[bl][kq * 4]) = v;
        }
    }
    __syncthreads();

    // outputs: [out(512) | h(51200) | c(51200)]
    if (ht == 0 && out_size >= NCLS * BATCH) {
        if (tid < TB * NCLS) {
            int bl = tid >> 1, cls = tid & 1;
            float acc = fc_b[cls];
            #pragma unroll 4
            for (int k = 0; k < HDIM; ++k)
                acc += s.hs[bl][k] * fc_w[cls * HDIM + k];
            out[(b0 + bl) * NCLS + cls] = sigf(acc);
        }
    }
    if (ht == 0 && out_size >= NCLS * BATCH + BATCH * HDIM) {
        for (int i = tid; i < TB * HDIM; i += NTHREADS) {
            int bl = i / HDIM, k = i - bl * HDIM;
            out[NCLS * BATCH + (size_t)(b0 + bl) * HDIM + k] = s.hs[bl][k];
        }
    }
    if (out_size >= NCLS * BATCH + 2 * BATCH * HDIM) {
        if (tid < TB * TH) {
            int b = tid / TH, hl = tid - (tid / TH) * TH;
            out[NCLS * BATCH + BATCH * HDIM + (size_t)(b0 + b) * HDIM + hd0 + hl]
                = s.c[b][hl];
        }
    }
}

extern "C" void kernel_launch(void* const* d_in, const int* in_sizes, int n_in,
                              void* d_out, int out_size) {
    const float* x     = (const float*)d_in[0];
    // d_in[1]=X_lengths (unused), d_in[2]=h0, d_in[3]=c0 (zeros, ignored)
    const float* W_ih  = (const float*)d_in[4];
    const float* W_hh  = (const float*)d_in[5];
    const float* b_ih  = (const float*)d_in[6];
    const float* b_hh  = (const float*)d_in[7];
    const float* fc_w  = (const float*)d_in[8];
    const float* fc_b  = (const float*)d_in[9];

    int smem = (int)sizeof(SmemLayout);
    cudaFuncSetAttribute(lstm_persistent,
                         cudaFuncAttributeMaxDynamicSharedMemorySize, smem);
    lstm_persistent<<<GRID_CTAS, NTHREADS, smem>>>(
        x, W_ih, W_hh, b_ih, b_hh, fc_w, fc_b, (float*)d_out, out_size);
}

// round 11
// speedup vs baseline: 1.5396x; 1.0582x over previous
#include <cuda_runtime.h>
#include <cstdint>

#define T_STEPS 2048
#define BATCH   256
#define HDIM    200
#define IN_DIM  27
#define NCLS    2

#define NGROUPS  16     // batch tiles; groups are mutually independent
#define GSIZE    8      // hd tiles per group -> 8-CTA barrier groups
#define GRID_CTAS (NGROUPS * GSIZE)   // 128 CTAs, 1/SM (SMEM-limited)
#define TB 16     // batches per CTA
#define TH 25     // hidden units per CTA
#define ROWS 100  // 4 gates * TH
#define ROWS_PAD 128
#define NTHREADS 512    // 16 warps; K split in 2 -> 2x4 register tile per thread
#define KQ_HALF  25     // 25 k-quads (=100 cols) per K-slice

// SMEM strides (floats): 16B-aligned rows, conflict-free quad-banks for LDS.128
#define WHH_S 212   // 53 quads/row, 53%8=5 -> 8 rows hit 8 distinct quad-banks
#define WIH_S 36    // 9 quads,  9%8=1
#define HS_S  204   // 51 quads, 51%8=3
#define XS_S  36
#define GS_S  17
#define RED_S 9     // stride 9 (odd) -> conflict-free partial exchange

struct SmemLayout {
    float whh[ROWS_PAD][WHH_S];   // 108544 B
    float wih[ROWS_PAD][WIH_S];   //  18432 B
    float hs[TB][HS_S];           //  13056 B (h staging, full HDIM per batch)
    float xs[2][TB][XS_S];        //   4608 B (double-buffered x)
    float bias[ROWS_PAD];         //    512 B
    float gates[ROWS_PAD][GS_S];  //   8704 B
    float c[TB][TH + 1];          //   1664 B
    float red[256][RED_S];        //   9216 B (K-split partial sums)
};
// total 164736 B -> 1 CTA/SM; 128 CTAs <= 148 SMs -> all co-resident.

__device__ float g_h[2][BATCH][HDIM];          // double-buffered h exchange (L2)
__device__ unsigned g_cnt[NGROUPS * 64];       // per-group arrive counters, 256B apart
__device__ unsigned g_ep [NGROUPS * 64];       // per-group epochs, 256B apart

typedef unsigned long long u64;

__device__ __forceinline__ void ffma2(u64& d, u64 a, u64 b) {
    asm("fma.rn.f32x2 %0, %1, %2, %3;" : "=l"(d) : "l"(a), "l"(b), "l"(d));
}
__device__ __forceinline__ float f2sum(u64 v) {
    return __uint_as_float((unsigned)v) + __uint_as_float((unsigned)(v >> 32));
}
__device__ __forceinline__ float sigf(float x) {
    float e = __expf(-x);
    return __fdividef(1.0f, 1.0f + e);
}
__device__ __forceinline__ float tanh_fast(float x) {
    float e = __expf(-2.0f * x);
    return __fdividef(2.0f, 1.0f + e) - 1.0f;
}
__device__ __forceinline__ unsigned ld_acq(const unsigned* p) {
    unsigned v;
    asm volatile("ld.acquire.gpu.u32 %0, [%1];" : "=r"(v) : "l"(p) : "memory");
    return v;
}
__device__ __forceinline__ unsigned atom_add_acqrel(unsigned* p, unsigned v) {
    unsigned o;
    asm volatile("atom.add.acq_rel.gpu.u32 %0, [%1], %2;"
                 : "=r"(o) : "l"(p), "r"(v) : "memory");
    return o;
}
__device__ __forceinline__ void bar_named(int id) {   // 256-thread named barrier
    asm volatile("bar.sync %0, 256;" :: "r"(id) : "memory");
}

__global__ void __launch_bounds__(NTHREADS, 1)
lstm_persistent(const float* __restrict__ x,      // [B][T][27]
                const float* __restrict__ W_ih,   // [800][27]
                const float* __restrict__ W_hh,   // [800][200]
                const float* __restrict__ b_ih,   // [800]
                const float* __restrict__ b_hh,   // [800]
                const float* __restrict__ fc_w,   // [2][200]
                const float* __restrict__ fc_b,   // [2]
                float* __restrict__ out, int out_size)
{
    extern __shared__ float smem_f[];
    SmemLayout& s = *reinterpret_cast<SmemLayout*>(smem_f);

    const int tid = threadIdx.x;
    const int bt  = blockIdx.x >> 3;   // group id (batch tile)
    const int ht  = blockIdx.x & 7;    // hd tile within group
    const int b0  = bt * TB;
    const int hd0 = ht * TH;

    unsigned* cnt = &g_cnt[bt * 64];
    unsigned* ep  = &g_ep [bt * 64];

    // ---- one-time staging: weight slices (row r = gate*25 + hl), bias, c=0 ----
    for (int i = tid; i < ROWS_PAD * HDIM; i += NTHREADS) {
        int r = i / HDIM, k = i - r * HDIM;
        float v = 0.0f;
        if (r < ROWS) {
            int gate = r / TH, hl = r - gate * TH;
            v = W_hh[(gate * HDIM + hd0 + hl) * HDIM + k];
        }
        s.whh[r][k] = v;
    }
    for (int i = tid; i < ROWS_PAD * 28; i += NTHREADS) {
        int r = i / 28, k = i - r * 28;
        float v = 0.0f;
        if (r < ROWS && k < IN_DIM) {
            int gate = r / TH, hl = r - gate * TH;
            v = W_ih[(gate * HDIM + hd0 + hl) * IN_DIM + k];
        }
        s.wih[r][k] = v;
    }
    if (tid < ROWS_PAD) {
        float v = 0.0f;
        if (tid < ROWS) {
            int gate = tid / TH, hl = tid - gate * TH;
            int gr = gate * HDIM + hd0 + hl;
            v = b_ih[gr] + b_hh[gr];
        }
        s.bias[tid] = v;
    }
    if (tid < TB * TH)                              // 400 items, 512 threads
        s.c[tid / TH][tid % TH] = 0.0f;
    for (int i = tid; i < TB * 28; i += NTHREADS) { // xs[0] for t=0
        int bl = i / 28, k = i - bl * 28;
        s.xs[0][bl][k] = (k < IN_DIM)
            ? x[((size_t)(b0 + bl) * T_STEPS + 0) * IN_DIM + k] : 0.0f;
    }

    // Barrier bookkeeping: read epoch BEFORE first arrive (race-free; relative
    // compare -> replay/wrap safe).
    unsigned seen = 0;
    if (tid == 0) seen = ld_acq(ep);
    __syncthreads();

    // K-split thread tile: ks = K-half; within half: rows (jb, jb+64) x 4 batches
    const int ks = tid >> 8;          // 0: k in [0,100); 1: k in [100,200)
    const int p  = tid & 255;
    const int jb = p >> 2;            // 0..63
    const int bb = p & 3;
    const int r0 = jb;
    const int r1 = jb + 64;
    const int kq0 = ks * KQ_HALF;     // quad offset of this K-slice

    // x prefetch coordinates (tid < 448 holds one padded x element)
    const int xp_bl = tid / 28;
    const int xp_k  = tid - xp_bl * 28;
    const bool xp_on = (tid < TB * 28);

    u64 a00, a01, a10, a11, a20, a21, a30, a31;

    // x-part (IN_DIM=27) computed by kslice 0 only; kslice 1 starts at zero.
    auto do_xpart = [&](int buf) {
        a00 = a01 = a10 = a11 = a20 = a21 = a30 = a31 = 0ull;
        if (ks == 0) {
            #pragma unroll
            for (int kq = 0; kq < 7; ++kq) {
                ulonglong2 W0 = *reinterpret_cast<const ulonglong2*>(&s.wih[r0][4 * kq]);
                ulonglong2 W1 = *reinterpret_cast<const ulonglong2*>(&s.wih[r1][4 * kq]);
                ulonglong2 V0 = *reinterpret_cast<const ulonglong2*>(&s.xs[buf][bb][4 * kq]);
                ulonglong2 V1 = *reinterpret_cast<const ulonglong2*>(&s.xs[buf][bb + 4][4 * kq]);
                ulonglong2 V2 = *reinterpret_cast<const ulonglong2*>(&s.xs[buf][bb + 8][4 * kq]);
                ulonglong2 V3 = *reinterpret_cast<const ulonglong2*>(&s.xs[buf][bb + 12][4 * kq]);
                ffma2(a00, V0.x, W0.x); ffma2(a00, V0.y, W0.y);
                ffma2(a01, V0.x, W1.x); ffma2(a01, V0.y, W1.y);
                ffma2(a10, V1.x, W0.x); ffma2(a10, V1.y, W0.y);
                ffma2(a11, V1.x, W1.x); ffma2(a11, V1.y, W1.y);
                ffma2(a20, V2.x, W0.x); ffma2(a20, V2.y, W0.y);
                ffma2(a21, V2.x, W1.x); ffma2(a21, V2.y, W1.y);
                ffma2(a30, V3.x, W0.x); ffma2(a30, V3.y, W0.y);
                ffma2(a31, V3.x, W1.x); ffma2(a31, V3.y, W1.y);
            }
        }
    };

    do_xpart(0);   // x-part for t=0 (xs[0] staged above, synced)

    for (int t = 0; t < T_STEPS; ++t) {
        // ---- prefetch x(t+1) into a register NOW: DRAM latency overlaps
        //      the wait + h staging + GEMM below ----
        float xreg = 0.0f;
        if (t + 1 < T_STEPS && xp_on && xp_k < IN_DIM)
            xreg = __ldg(&x[((size_t)(b0 + xp_bl) * T_STEPS + (t + 1)) * IN_DIM + xp_k]);

        if (t > 0) {
            // ---- wait for peers' h(t-1) ----
            if (tid == 0) {
                unsigned v;
                do { v = ld_acq(ep); } while (v == seen);
                seen = v;
            }
            __syncthreads();   // tid0's acquire ordered before everyone's reads

            // ---- stage this K-half's h quads; sync only within the half ----
            {
                const float* hb = &g_h[t & 1][b0][0];
                // half items: TB batches x KQ_HALF quads = 400 float4 over 256 thr
                for (int i = p; i < TB * KQ_HALF; i += 256) {
                    int bl = i / KQ_HALF, kq = kq0 + (i - bl * KQ_HALF);
                    float4 v = __ldcg(reinterpret_cast<const float4*>(
                                          hb + (size_t)bl * HDIM + 4 * kq));
                    *reinterpret_cast<float4*>(&s.hs[bl][4 * kq]) = v;
                }
                bar_named(8 + ks);   // 256-thread barrier per K-half
            }

            // ---- recurrent GEMM: 25 k-quads (this K-slice) over 2x4 tile ----
            #pragma unroll 5
            for (int kq = 0; kq < KQ_HALF; ++kq) {
                int q = kq0 + kq;
                ulonglong2 W0 = *reinterpret_cast<const ulonglong2*>(&s.whh[r0][4 * q]);
                ulonglong2 W1 = *reinterpret_cast<const ulonglong2*>(&s.whh[r1][4 * q]);
                ulonglong2 V0 = *reinterpret_cast<const ulonglong2*>(&s.hs[bb][4 * q]);
                ulonglong2 V1 = *reinterpret_cast<const ulonglong2*>(&s.hs[bb + 4][4 * q]);
                ulonglong2 V2 = *reinterpret_cast<const ulonglong2*>(&s.hs[bb + 8][4 * q]);
                ulonglong2 V3 = *reinterpret_cast<const ulonglong2*>(&s.hs[bb + 12][4 * q]);
                ffma2(a00, V0.x, W0.x); ffma2(a00, V0.y, W0.y);
                ffma2(a01, V0.x, W1.x); ffma2(a01, V0.y, W1.y);
                ffma2(a10, V1.x, W0.x); ffma2(a10, V1.y, W0.y);
                ffma2(a11, V1.x, W1.x); ffma2(a11, V1.y, W1.y);
                ffma2(a20, V2.x, W0.x); ffma2(a20, V2.y, W0.y);
                ffma2(a21, V2.x, W1.x); ffma2(a21, V2.y, W1.y);
                ffma2(a30, V3.x, W0.x); ffma2(a30, V3.y, W0.y);
                ffma2(a31, V3.x, W1.x); ffma2(a31, V3.y, W1.y);
            }
        }

        // ---- K-split reduction + gate scatter (bias folded in) ----
        if (ks == 1) {
            s.red[p][0] = f2sum(a00);
            s.red[p][1] = f2sum(a01);
            s.red[p][2] = f2sum(a10);
            s.red[p][3] = f2sum(a11);
            s.red[p][4] = f2sum(a20);
            s.red[p][5] = f2sum(a21);
            s.red[p][6] = f2sum(a30);
            s.red[p][7] = f2sum(a31);
        }
        __syncthreads();
        if (ks == 0) {
            float bs0 = s.bias[r0], bs1 = s.bias[r1];
            s.gates[r0][bb]      = f2sum(a00) + s.red[p][0] + bs0;
            s.gates[r1][bb]      = f2sum(a01) + s.red[p][1] + bs1;
            s.gates[r0][bb + 4]  = f2sum(a10) + s.red[p][2] + bs0;
            s.gates[r1][bb + 4]  = f2sum(a11) + s.red[p][3] + bs1;
            s.gates[r0][bb + 8]  = f2sum(a20) + s.red[p][4] + bs0;
            s.gates[r1][bb + 8]  = f2sum(a21) + s.red[p][5] + bs1;
            s.gates[r0][bb + 12] = f2sum(a30) + s.red[p][6] + bs0;
            s.gates[r1][bb + 12] = f2sum(a31) + s.red[p][7] + bs1;
        }
        __syncthreads();

        // ---- cell update (400 items) + x(t+1) STS from registers, one sync ----
        const int nxt = (t + 1) & 1;
        if (tid < TB * TH) {
            int b = tid / TH, hl = tid - (tid / TH) * TH;
            float gi = sigf(s.gates[hl][b]);
            float gf = sigf(s.gates[TH + hl][b]);
            float gg = tanh_fast(s.gates[2 * TH + hl][b]);
            float go = sigf(s.gates[3 * TH + hl][b]);
            float c = gf * s.c[b][hl] + gi * gg;
            s.c[b][hl] = c;
            __stcg(&g_h[nxt][b0 + b][hd0 + hl], go * tanh_fast(c));
        }
        if (t + 1 < T_STEPS && xp_on)
            s.xs[nxt][xp_bl][xp_k] = xreg;     // register -> SMEM, no DRAM wait

        __syncthreads();   // covers stcg (for arrive-release) and xs STS

        if (tid == 0) {
            unsigned old = atom_add_acqrel(cnt, 1u);
            if (old == GSIZE - 1) {
                atomicExch(cnt, 0u);          // ordered before flip by release below
                atom_add_acqrel(ep, 1u);      // flip
            }
        }

        // ---- x-part for t+1 (hidden under peer skew) ----
        if (t + 1 < T_STEPS) do_xpart(nxt);
    }

    // ---- final wait: peers' h(2047) (stored in g_h[0]) visible ----
    if (tid == 0) {
        unsigned v;
        do { v = ld_acq(ep); } while (v == seen);
        seen = v;
    }
    __syncthreads();
    {
        const float4* hsrc = reinterpret_cast<const float4*>(&g_h[0][b0][0]);
        for (int i = tid; i < TB * (HDIM / 4); i += NTHREADS) {
            int bl = i / 50, kq = i - bl * 50;
            float4 v = __ldcg(hsrc + i);
            *reinterpret_cast<float4*>(&s.hs[bl][kq * 4]) = v;
        }
    }
    __syncthreads();

    // outputs: [out(512) | h(51200) | c(51200)]
    if (ht == 0 && out_size >= NCLS * BATCH) {
        if (tid < TB * NCLS) {
            int bl = tid >> 1, cls = tid & 1;
            float acc = fc_b[cls];
            #pragma unroll 4
            for (int k = 0; k < HDIM; ++k)
                acc += s.hs[bl][k] * fc_w[cls * HDIM + k];
            out[(b0 + bl) * NCLS + cls] = sigf(acc);
        }
    }
    if (ht == 0 && out_size >= NCLS * BATCH + BATCH * HDIM) {
        for (int i = tid; i < TB * HDIM; i += NTHREADS) {
            int bl = i / HDIM, k = i - bl * HDIM;
            out[NCLS * BATCH + (size_t)(b0 + bl) * HDIM + k] = s.hs[bl][k];
        }
    }
    if (out_size >= NCLS * BATCH + 2 * BATCH * HDIM) {
        if (tid < TB * TH) {
            int b = tid / TH, hl = tid - (tid / TH) * TH;
            out[NCLS * BATCH + BATCH * HDIM + (size_t)(b0 + b) * HDIM + hd0 + hl]
                = s.c[b][hl];
        }
    }
}

extern "C" void kernel_launch(void* const* d_in, const int* in_sizes, int n_in,
                              void* d_out, int out_size) {
    const float* x     = (const float*)d_in[0];
    // d_in[1]=X_lengths (unused), d_in[2]=h0, d_in[3]=c0 (zeros, ignored)
    const float* W_ih  = (const float*)d_in[4];
    const float* W_hh  = (const float*)d_in[5];
    const float* b_ih  = (const float*)d_in[6];
    const float* b_hh  = (const float*)d_in[7];
    const float* fc_w  = (const float*)d_in[8];
    const float* fc_b  = (const float*)d_in[9];

    int smem = (int)sizeof(SmemLayout);
    cudaFuncSetAttribute(lstm_persistent,
                         cudaFuncAttributeMaxDynamicSharedMemorySize, smem);
    lstm_persistent<<<GRID_CTAS, NTHREADS, smem>>>(
        x, W_ih, W_hh, b_ih, b_hh, fc_w, fc_b, (float*)d_out, out_size);
}

// round 13
// speedup vs baseline: 1.8509x; 1.2022x over previous
#include <cuda_runtime.h>
#include <cstdint>

#define T_STEPS 2048
#define BATCH   256
#define HDIM    200
#define IN_DIM  27
#define NCLS    2

#define NGROUPS  16     // batch tiles; groups are mutually independent
#define GSIZE    8      // hd tiles per group -> 8-CTA barrier groups
#define GRID_CTAS (NGROUPS * GSIZE)   // 128 CTAs, 1/SM (SMEM-limited)
#define TB 16     // batches per CTA
#define TH 25     // hidden units per CTA
#define ROWS 100  // 4 gates * TH
#define ROWS_PAD 128
#define NTHREADS 512    // 16 warps; K split 4 ways; 4x4 register tile per thread

// SMEM strides (floats): 16B-aligned rows, conflict-free quad-banks for LDS.128
#define WHH_S 212   // 53 quads/row, 53%8=5 -> 8 rows hit 8 distinct quad-banks
#define WIH_S 36    // 9 quads,  9%8=1
#define HS_S  204   // 51 quads, 51%8=3
#define XS_S  36
#define GS_S  17
#define RED_S 17    // odd stride -> <=2-way on partial exchange

struct SmemLayout {
    float whh[ROWS_PAD][WHH_S];      // 108544 B
    float wih[ROWS_PAD][WIH_S];      //  18432 B
    float hs[TB][HS_S];              //  13056 B (h staging, full HDIM per batch)
    float xs[2][TB][XS_S];           //   4608 B (double-buffered x)
    float bias[ROWS_PAD];            //    512 B
    float gates[ROWS_PAD][GS_S];     //   8704 B
    float c[TB][TH + 1];             //   1664 B
    float red[3][ROWS_PAD][RED_S];   //  26112 B (K-split partials, slices 1..3)
};
// total 181632 B -> 1 CTA/SM; 128 CTAs <= 148 SMs -> all co-resident.

__device__ float g_h[2][BATCH][HDIM];          // double-buffered h exchange (L2)
__device__ unsigned g_cnt[NGROUPS * 64];       // per-group arrive counters, 256B apart
__device__ unsigned g_ep [NGROUPS * 64];       // per-group epochs, 256B apart

typedef unsigned long long u64;

__device__ __forceinline__ void ffma2(u64& d, u64 a, u64 b) {
    asm("fma.rn.f32x2 %0, %1, %2, %3;" : "=l"(d) : "l"(a), "l"(b), "l"(d));
}
__device__ __forceinline__ float f2sum(u64 v) {
    return __uint_as_float((unsigned)v) + __uint_as_float((unsigned)(v >> 32));
}
__device__ __forceinline__ float sigf(float x) {
    float e = __expf(-x);
    return __fdividef(1.0f, 1.0f + e);
}
__device__ __forceinline__ float tanh_fast(float x) {
    float e = __expf(-2.0f * x);
    return __fdividef(2.0f, 1.0f + e) - 1.0f;
}
__device__ __forceinline__ unsigned ld_acq(const unsigned* p) {
    unsigned v;
    asm volatile("ld.acquire.gpu.u32 %0, [%1];" : "=r"(v) : "l"(p) : "memory");
    return v;
}
__device__ __forceinline__ unsigned atom_add_acqrel(unsigned* p, unsigned v) {
    unsigned o;
    asm volatile("atom.add.acq_rel.gpu.u32 %0, [%1], %2;"
                 : "=r"(o) : "l"(p), "r"(v) : "memory");
    return o;
}
__device__ __forceinline__ void bar_named128(int id) {  // 128-thread named barrier
    asm volatile("bar.sync %0, 128;" :: "r"(id) : "memory");
}

__global__ void __launch_bounds__(NTHREADS, 1)
lstm_persistent(const float* __restrict__ x,      // [B][T][27]
                const float* __restrict__ W_ih,   // [800][27]
                const float* __restrict__ W_hh,   // [800][200]
                const float* __restrict__ b_ih,   // [800]
                const float* __restrict__ b_hh,   // [800]
                const float* __restrict__ fc_w,   // [2][200]
                const float* __restrict__ fc_b,   // [2]
                float* __restrict__ out, int out_size)
{
    extern __shared__ float smem_f[];
    SmemLayout& s = *reinterpret_cast<SmemLayout*>(smem_f);

    const int tid = threadIdx.x;
    const int bt  = blockIdx.x >> 3;   // group id (batch tile)
    const int ht  = blockIdx.x & 7;    // hd tile within group
    const int b0  = bt * TB;
    const int hd0 = ht * TH;

    unsigned* cnt = &g_cnt[bt * 64];
    unsigned* ep  = &g_ep [bt * 64];

    // ---- one-time staging: weight slices (row r = gate*25 + hl), bias, c=0 ----
    for (int i = tid; i < ROWS_PAD * HDIM; i += NTHREADS) {
        int r = i / HDIM, k = i - r * HDIM;
        float v = 0.0f;
        if (r < ROWS) {
            int gate = r / TH, hl = r - gate * TH;
            v = W_hh[(gate * HDIM + hd0 + hl) * HDIM + k];
        }
        s.whh[r][k] = v;
    }
    for (int i = tid; i < ROWS_PAD * 28; i += NTHREADS) {
        int r = i / 28, k = i - r * 28;
        float v = 0.0f;
        if (r < ROWS && k < IN_DIM) {
            int gate = r / TH, hl = r - gate * TH;
            v = W_ih[(gate * HDIM + hd0 + hl) * IN_DIM + k];
        }
        s.wih[r][k] = v;
    }
    if (tid < ROWS_PAD) {
        float v = 0.0f;
        if (tid < ROWS) {
            int gate = tid / TH, hl = tid - gate * TH;
            int gr = gate * HDIM + hd0 + hl;
            v = b_ih[gr] + b_hh[gr];
        }
        s.bias[tid] = v;
    }
    if (tid < TB * TH)                              // 400 items, 512 threads
        s.c[tid / TH][tid % TH] = 0.0f;
    for (int i = tid; i < TB * 28; i += NTHREADS) { // xs[0] for t=0
        int bl = i / 28, k = i - bl * 28;
        s.xs[0][bl][k] = (k < IN_DIM)
            ? x[((size_t)(b0 + bl) * T_STEPS + 0) * IN_DIM + k] : 0.0f;
    }

    // Barrier bookkeeping: read epoch BEFORE first arrive (race-free; relative
    // compare -> replay/wrap safe).
    unsigned seen = 0;
    if (tid == 0) seen = ld_acq(ep);
    __syncthreads();

    // K-split-4 thread tile: ks = slice; rows {jb,jb+32,jb+64,jb+96} x 4 batches
    const int ks = tid >> 7;          // 0..3
    const int p  = tid & 127;
    const int jb = p >> 2;            // 0..31
    const int bb = p & 3;
    const int r0g = jb, r1g = jb + 32, r2g = jb + 64, r3g = jb + 96;
    // R13 FIX: 50 h-quads total (HDIM=200), not 25.
    // ks0:[0,14) ks1:[14,28) ks2:[28,42) ks3:[42,50) (+7-quad x-part on ks3)
    const int kq_lo = 14 * ks;
    const int kq_hi = (ks < 3) ? (14 * ks + 14) : 50;
    const int nq    = kq_hi - kq_lo;           // 14,14,14,8

    // ks0 caches its bias values (constant over time)
    float bs0 = 0, bs1 = 0, bs2 = 0, bs3 = 0;
    if (ks == 0) {
        bs0 = s.bias[r0g]; bs1 = s.bias[r1g];
        bs2 = s.bias[r2g]; bs3 = s.bias[r3g];
    }

    // x prefetch coordinates (tid < 448 holds one padded x element)
    const int xp_bl = tid / 28;
    const int xp_k  = tid - xp_bl * 28;
    const bool xp_on = (tid < TB * 28);

    // 4x4 accumulator tile [row m][batch n]
    u64 A00, A01, A02, A03, A10, A11, A12, A13;
    u64 A20, A21, A22, A23, A30, A31, A32, A33;

#define GEMM_QUAD(WARR, VARR, Q)                                               \
    {                                                                          \
        ulonglong2 W0 = *reinterpret_cast<const ulonglong2*>(&WARR[r0g][4*(Q)]);\
        ulonglong2 W1 = *reinterpret_cast<const ulonglong2*>(&WARR[r1g][4*(Q)]);\
        ulonglong2 W2 = *reinterpret_cast<const ulonglong2*>(&WARR[r2g][4*(Q)]);\
        ulonglong2 W3 = *reinterpret_cast<const ulonglong2*>(&WARR[r3g][4*(Q)]);\
        ulonglong2 V0 = *reinterpret_cast<const ulonglong2*>(&VARR[bb][4*(Q)]);\
        ulonglong2 V1 = *reinterpret_cast<const ulonglong2*>(&VARR[bb+4][4*(Q)]);\
        ulonglong2 V2 = *reinterpret_cast<const ulonglong2*>(&VARR[bb+8][4*(Q)]);\
        ulonglong2 V3 = *reinterpret_cast<const ulonglong2*>(&VARR[bb+12][4*(Q)]);\
        ffma2(A00,V0.x,W0.x); ffma2(A00,V0.y,W0.y);                            \
        ffma2(A01,V1.x,W0.x); ffma2(A01,V1.y,W0.y);                            \
        ffma2(A02,V2.x,W0.x); ffma2(A02,V2.y,W0.y);                            \
        ffma2(A03,V3.x,W0.x); ffma2(A03,V3.y,W0.y);                            \
        ffma2(A10,V0.x,W1.x); ffma2(A10,V0.y,W1.y);                            \
        ffma2(A11,V1.x,W1.x); ffma2(A11,V1.y,W1.y);                            \
        ffma2(A12,V2.x,W1.x); ffma2(A12,V2.y,W1.y);                            \
        ffma2(A13,V3.x,W1.x); ffma2(A13,V3.y,W1.y);                            \
        ffma2(A20,V0.x,W2.x); ffma2(A20,V0.y,W2.y);                            \
        ffma2(A21,V1.x,W2.x); ffma2(A21,V1.y,W2.y);                            \
        ffma2(A22,V2.x,W2.x); ffma2(A22,V2.y,W2.y);                            \
        ffma2(A23,V3.x,W2.x); ffma2(A23,V3.y,W2.y);                            \
        ffma2(A30,V0.x,W3.x); ffma2(A30,V0.y,W3.y);                            \
        ffma2(A31,V1.x,W3.x); ffma2(A31,V1.y,W3.y);                            \
        ffma2(A32,V2.x,W3.x); ffma2(A32,V2.y,W3.y);                            \
        ffma2(A33,V3.x,W3.x); ffma2(A33,V3.y,W3.y);                            \
    }

    // reset accumulators + (slice 3 only) x-part for buffer `buf`
    auto do_xpart = [&](int buf) {
        A00=A01=A02=A03=A10=A11=A12=A13=0ull;
        A20=A21=A22=A23=A30=A31=A32=A33=0ull;
        if (ks == 3) {
            #pragma unroll
            for (int q = 0; q < 7; ++q) GEMM_QUAD(s.wih, s.xs[buf], q);
        }
    };

    do_xpart(0);   // x-part for t=0 (xs[0] staged above, synced)

    for (int t = 0; t < T_STEPS; ++t) {
        // prefetch x(t+1): DRAM latency overlaps wait + staging + GEMM
        float xreg = 0.0f;
        if (t + 1 < T_STEPS && xp_on && xp_k < IN_DIM)
            xreg = __ldg(&x[((size_t)(b0 + xp_bl) * T_STEPS + (t + 1)) * IN_DIM + xp_k]);

        if (t > 0) {
            // ---- wait for peers' h(t-1) ----
            if (tid == 0) {
                unsigned v;
                do { v = ld_acq(ep); } while (v == seen);
                seen = v;
            }
            __syncthreads();   // tid0's acquire ordered before everyone's reads

            // ---- stage this slice's h quads; sync within the slice only ----
            {
                const float* hb = &g_h[t & 1][b0][0];
                for (int i = p; i < TB * nq; i += 128) {
                    int bl = i / nq, kq = kq_lo + (i - bl * nq);
                    float4 v = __ldcg(reinterpret_cast<const float4*>(
                                          hb + (size_t)bl * HDIM + 4 * kq));
                    *reinterpret_cast<float4*>(&s.hs[bl][4 * kq]) = v;
                }
                bar_named128(8 + ks);
            }

            // ---- recurrent GEMM over this slice's quads ----
            #pragma unroll 2
            for (int q = kq_lo; q < kq_hi; ++q) GEMM_QUAD(s.whh, s.hs, q);
        }

        // ---- K-split-4 reduction: slices 1..3 export, slice 0 gathers ----
        if (ks != 0) {
            float (*rd)[RED_S] = s.red[ks - 1];
            rd[r0g][bb]      = f2sum(A00); rd[r0g][bb + 4]  = f2sum(A01);
            rd[r0g][bb + 8]  = f2sum(A02); rd[r0g][bb + 12] = f2sum(A03);
            rd[r1g][bb]      = f2sum(A10); rd[r1g][bb + 4]  = f2sum(A11);
            rd[r1g][bb + 8]  = f2sum(A12); rd[r1g][bb + 12] = f2sum(A13);
            rd[r2g][bb]      = f2sum(A20); rd[r2g][bb + 4]  = f2sum(A21);
            rd[r2g][bb + 8]  = f2sum(A22); rd[r2g][bb + 12] = f2sum(A23);
            rd[r3g][bb]      = f2sum(A30); rd[r3g][bb + 4]  = f2sum(A31);
            rd[r3g][bb + 8]  = f2sum(A32); rd[r3g][bb + 12] = f2sum(A33);
        }
        __syncthreads();
        if (ks == 0) {
            #define GATHER(Rg, Acc, Bn, BS)                                    \
                s.gates[Rg][Bn] = f2sum(Acc) + s.red[0][Rg][Bn]                \
                                + s.red[1][Rg][Bn] + s.red[2][Rg][Bn] + BS;
            GATHER(r0g, A00, bb, bs0)      GATHER(r0g, A01, bb + 4, bs0)
            GATHER(r0g, A02, bb + 8, bs0)  GATHER(r0g, A03, bb + 12, bs0)
            GATHER(r1g, A10, bb, bs1)      GATHER(r1g, A11, bb + 4, bs1)
            GATHER(r1g, A12, bb + 8, bs1)  GATHER(r1g, A13, bb + 12, bs1)
            GATHER(r2g, A20, bb, bs2)      GATHER(r2g, A21, bb + 4, bs2)
            GATHER(r2g, A22, bb + 8, bs2)  GATHER(r2g, A23, bb + 12, bs2)
            GATHER(r3g, A30, bb, bs3)      GATHER(r3g, A31, bb + 4, bs3)
            GATHER(r3g, A32, bb + 8, bs3)  GATHER(r3g, A33, bb + 12, bs3)
            #undef GATHER
        }
        __syncthreads();

        // ---- cell update (400 items) + x(t+1) STS, one sync ----
        const int nxt = (t + 1) & 1;
        if (tid < TB * TH) {
            int b = tid / TH, hl = tid - (tid / TH) * TH;
            float gi = sigf(s.gates[hl][b]);
            float gf = sigf(s.gates[TH + hl][b]);
            float gg = tanh_fast(s.gates[2 * TH + hl][b]);
            float go = sigf(s.gates[3 * TH + hl][b]);
            float c = gf * s.c[b][hl] + gi * gg;
            s.c[b][hl] = c;
            __stcg(&g_h[nxt][b0 + b][hd0 + hl], go * tanh_fast(c));
        }
        if (t + 1 < T_STEPS && xp_on)
            s.xs[nxt][xp_bl][xp_k] = xreg;

        __syncthreads();   // covers stcg (for arrive-release) and xs STS

        if (tid == 0) {
            unsigned old = atom_add_acqrel(cnt, 1u);
            if (old == GSIZE - 1) {
                atomicExch(cnt, 0u);
                atom_add_acqrel(ep, 1u);      // flip
            }
        }

        // ---- x-part for t+1 (slice 3; hidden under peer skew) ----
        if (t + 1 < T_STEPS) do_xpart(nxt);
    }

    // ---- final wait: peers' h(2047) (stored in g_h[0]) visible ----
    if (tid == 0) {
        unsigned v;
        do { v = ld_acq(ep); } while (v == seen);
        seen = v;
    }
    __syncthreads();
    {
        const float4* hsrc = reinterpret_cast<const float4*>(&g_h[0][b0][0]);
        for (int i = tid; i < TB * (HDIM / 4); i += NTHREADS) {
            int bl = i / 50, kq = i - bl * 50;
            float4 v = __ldcg(hsrc + i);
            *reinterpret_cast<float4*>(&s.hs[bl][kq * 4]) = v;
        }
    }
    __syncthreads();

    // outputs: [out(512) | h(51200) | c(51200)]
    if (ht == 0 && out_size >= NCLS * BATCH) {
        if (tid < TB * NCLS) {
            int bl = tid >> 1, cls = tid & 1;
            float acc = fc_b[cls];
            #pragma unroll 4
            for (int k = 0; k < HDIM; ++k)
                acc += s.hs[bl][k] * fc_w[cls * HDIM + k];
            out[(b0 + bl) * NCLS + cls] = sigf(acc);
        }
    }
    if (ht == 0 && out_size >= NCLS * BATCH + BATCH * HDIM) {
        for (int i = tid; i < TB * HDIM; i += NTHREADS) {
            int bl = i / HDIM, k = i - bl * HDIM;
            out[NCLS * BATCH + (size_t)(b0 + bl) * HDIM + k] = s.hs[bl][k];
        }
    }
    if (out_size >= NCLS * BATCH + 2 * BATCH * HDIM) {
        if (tid < TB * TH) {
            int b = tid / TH, hl = tid - (tid / TH) * TH;
            out[NCLS * BATCH + BATCH * HDIM + (size_t)(b0 + b) * HDIM + hd0 + hl]
                = s.c[b][hl];
        }
    }
}

extern "C" void kernel_launch(void* const* d_in, const int* in_sizes, int n_in,
                              void* d_out, int out_size) {
    const float* x     = (const float*)d_in[0];
    // d_in[1]=X_lengths (unused), d_in[2]=h0, d_in[3]=c0 (zeros, ignored)
    const float* W_ih  = (const float*)d_in[4];
    const float* W_hh  = (const float*)d_in[5];
    const float* b_ih  = (const float*)d_in[6];
    const float* b_hh  = (const float*)d_in[7];
    const float* fc_w  = (const float*)d_in[8];
    const float* fc_b  = (const float*)d_in[9];

    int smem = (int)sizeof(SmemLayout);
    cudaFuncSetAttribute(lstm_persistent,
                         cudaFuncAttributeMaxDynamicSharedMemorySize, smem);
    lstm_persistent<<<GRID_CTAS, NTHREADS, smem>>>(
        x, W_ih, W_hh, b_ih, b_hh, fc_w, fc_b, (float*)d_out, out_size);
}

// round 14
// speedup vs baseline: 2.0736x; 1.1203x over previous
#include <cuda_runtime.h>
#include <cstdint>

#define T_STEPS 2048
#define BATCH   256
#define HDIM    200
#define IN_DIM  27
#define NCLS    2

#define NGROUPS  16     // batch tiles; groups are mutually independent
#define GSIZE    8      // hd tiles per group -> 8-CTA barrier groups
#define GRID_CTAS (NGROUPS * GSIZE)   // 128 CTAs, 1/SM (SMEM-limited)
#define TB 16     // batches per CTA
#define TH 25     // hidden units per CTA
#define ROWS 100  // 4 gates * TH
#define ROWS_PAD 128
#define NTHREADS 512    // 16 warps; K split 4 ways; 4x4 register tile per thread

// SMEM strides (floats): 16B-aligned rows, conflict-free quad-banks for LDS.128
#define WHH_S 212   // 53 quads/row, 53%8=5 -> 8 consecutive rows hit 8 banks
#define WIH_S 36    // 9 quads,  9%8=1
#define HS_S  204   // 51 quads, 51%8=3
#define XS_S  36
#define RED_S 17    // odd stride -> low-conflict partial exchange

struct SmemLayout {
    float whh[ROWS_PAD][WHH_S];      // 108544 B
    float wih[ROWS_PAD][WIH_S];      //  18432 B
    float hs[TB][HS_S];              //  13056 B (h staging, full HDIM per batch)
    float xs[2][TB][XS_S];           //   4608 B (double-buffered x)
    float bias[ROWS_PAD];            //    512 B
    float red[3][ROWS_PAD][RED_S];   //  26112 B (K-split partials, slices 1..3)
};
// total 171264 B -> 1 CTA/SM; 128 CTAs <= 148 SMs -> all co-resident.

__device__ float g_h[2][BATCH][HDIM];          // double-buffered h exchange (L2)
__device__ unsigned g_cnt[NGROUPS * 64];       // per-group arrive counters, 256B apart
__device__ unsigned g_ep [NGROUPS * 64];       // per-group epochs, 256B apart

typedef unsigned long long u64;

__device__ __forceinline__ void ffma2(u64& d, u64 a, u64 b) {
    asm("fma.rn.f32x2 %0, %1, %2, %3;" : "=l"(d) : "l"(a), "l"(b), "l"(d));
}
__device__ __forceinline__ float f2sum(u64 v) {
    return __uint_as_float((unsigned)v) + __uint_as_float((unsigned)(v >> 32));
}
__device__ __forceinline__ float sigf(float x) {
    float e = __expf(-x);
    return __fdividef(1.0f, 1.0f + e);
}
__device__ __forceinline__ float tanh_fast(float x) {
    float e = __expf(-2.0f * x);
    return __fdividef(2.0f, 1.0f + e) - 1.0f;
}
__device__ __forceinline__ unsigned ld_acq(const unsigned* p) {
    unsigned v;
    asm volatile("ld.acquire.gpu.u32 %0, [%1];" : "=r"(v) : "l"(p) : "memory");
    return v;
}
__device__ __forceinline__ unsigned atom_add_acqrel(unsigned* p, unsigned v) {
    unsigned o;
    asm volatile("atom.add.acq_rel.gpu.u32 %0, [%1], %2;"
                 : "=r"(o) : "l"(p), "r"(v) : "memory");
    return o;
}
__device__ __forceinline__ void bar_named128(int id) {  // 128-thread named barrier
    asm volatile("bar.sync %0, 128;" :: "r"(id) : "memory");
}

__global__ void __launch_bounds__(NTHREADS, 1)
lstm_persistent(const float* __restrict__ x,      // [B][T][27]
                const float* __restrict__ W_ih,   // [800][27]
                const float* __restrict__ W_hh,   // [800][200]
                const float* __restrict__ b_ih,   // [800]
                const float* __restrict__ b_hh,   // [800]
                const float* __restrict__ fc_w,   // [2][200]
                const float* __restrict__ fc_b,   // [2]
                float* __restrict__ out, int out_size)
{
    extern __shared__ float smem_f[];
    SmemLayout& s = *reinterpret_cast<SmemLayout*>(smem_f);

    const int tid = threadIdx.x;
    const int bt  = blockIdx.x >> 3;   // group id (batch tile)
    const int ht  = blockIdx.x & 7;    // hd tile within group
    const int b0  = bt * TB;
    const int hd0 = ht * TH;

    unsigned* cnt = &g_cnt[bt * 64];
    unsigned* ep  = &g_ep [bt * 64];

    // ---- one-time staging: weight slices (row r = gate*25 + hl), bias ----
    for (int i = tid; i < ROWS_PAD * HDIM; i += NTHREADS) {
        int r = i / HDIM, k = i - r * HDIM;
        float v = 0.0f;
        if (r < ROWS) {
            int gate = r / TH, hl = r - gate * TH;
            v = W_hh[(gate * HDIM + hd0 + hl) * HDIM + k];
        }
        s.whh[r][k] = v;
    }
    for (int i = tid; i < ROWS_PAD * 28; i += NTHREADS) {
        int r = i / 28, k = i - r * 28;
        float v = 0.0f;
        if (r < ROWS && k < IN_DIM) {
            int gate = r / TH, hl = r - gate * TH;
            v = W_ih[(gate * HDIM + hd0 + hl) * IN_DIM + k];
        }
        s.wih[r][k] = v;
    }
    if (tid < ROWS_PAD) {
        float v = 0.0f;
        if (tid < ROWS) {
            int gate = tid / TH, hl = tid - gate * TH;
            int gr = gate * HDIM + hd0 + hl;
            v = b_ih[gr] + b_hh[gr];
        }
        s.bias[tid] = v;
    }
    for (int i = tid; i < TB * 28; i += NTHREADS) { // xs[0] for t=0
        int bl = i / 28, k = i - bl * 28;
        s.xs[0][bl][k] = (k < IN_DIM)
            ? x[((size_t)(b0 + bl) * T_STEPS + 0) * IN_DIM + k] : 0.0f;
    }

    // Barrier bookkeeping: read epoch BEFORE first arrive (race-free; relative
    // compare -> replay/wrap safe).
    unsigned seen = 0;
    if (tid == 0) seen = ld_acq(ep);
    __syncthreads();

    // K-split-4, gate-aligned tile: ks = slice; rows {jb, jb+25, jb+50, jb+75}
    // = gates {i,f,g,o} of hidden unit jb. Active rows only for jb < 25.
    const int ks = tid >> 7;          // 0..3
    const int p  = tid & 127;
    const int jb = p >> 2;            // 0..31 (25..31 = padding rows)
    const int bb = p & 3;
    const bool act = (jb < TH);       // owns real rows
    const int r0g = jb, r1g = jb + 25, r2g = jb + 50, r3g = jb + 75;
    // h-quad slices: ks0:[0,14) ks1:[14,28) ks2:[28,42) ks3:[42,50) (+x on ks3)
    const int kq_lo = 14 * ks;

    // ks0 caches bias (i,f,g,o of unit jb) and keeps c in registers
    float bsi = 0, bsf = 0, bsg = 0, bso = 0;
    float creg0 = 0, creg1 = 0, creg2 = 0, creg3 = 0;
    if (ks == 0 && act) {
        bsi = s.bias[r0g]; bsf = s.bias[r1g];
        bsg = s.bias[r2g]; bso = s.bias[r3g];
    }

    // x prefetch coordinates (tid < 448 holds one padded x element)
    const int xp_bl = tid / 28;
    const int xp_k  = tid - xp_bl * 28;
    const bool xp_on = (tid < TB * 28);

    // 4x4 accumulator tile [gate][batch]
    u64 A00, A01, A02, A03, A10, A11, A12, A13;
    u64 A20, A21, A22, A23, A30, A31, A32, A33;

#define GEMM_QUAD(WARR, VARR, Q)                                               \
    {                                                                          \
        ulonglong2 W0 = *reinterpret_cast<const ulonglong2*>(&WARR[r0g][4*(Q)]);\
        ulonglong2 W1 = *reinterpret_cast<const ulonglong2*>(&WARR[r1g][4*(Q)]);\
        ulonglong2 W2 = *reinterpret_cast<const ulonglong2*>(&WARR[r2g][4*(Q)]);\
        ulonglong2 W3 = *reinterpret_cast<const ulonglong2*>(&WARR[r3g][4*(Q)]);\
        ulonglong2 V0 = *reinterpret_cast<const ulonglong2*>(&VARR[bb][4*(Q)]);\
        ulonglong2 V1 = *reinterpret_cast<const ulonglong2*>(&VARR[bb+4][4*(Q)]);\
        ulonglong2 V2 = *reinterpret_cast<const ulonglong2*>(&VARR[bb+8][4*(Q)]);\
        ulonglong2 V3 = *reinterpret_cast<const ulonglong2*>(&VARR[bb+12][4*(Q)]);\
        ffma2(A00,V0.x,W0.x); ffma2(A00,V0.y,W0.y);                            \
        ffma2(A01,V1.x,W0.x); ffma2(A01,V1.y,W0.y);                            \
        ffma2(A02,V2.x,W0.x); ffma2(A02,V2.y,W0.y);                            \
        ffma2(A03,V3.x,W0.x); ffma2(A03,V3.y,W0.y);                            \
        ffma2(A10,V0.x,W1.x); ffma2(A10,V0.y,W1.y);                            \
        ffma2(A11,V1.x,W1.x); ffma2(A11,V1.y,W1.y);                            \
        ffma2(A12,V2.x,W1.x); ffma2(A12,V2.y,W1.y);                            \
        ffma2(A13,V3.x,W1.x); ffma2(A13,V3.y,W1.y);                            \
        ffma2(A20,V0.x,W2.x); ffma2(A20,V0.y,W2.y);                            \
        ffma2(A21,V1.x,W2.x); ffma2(A21,V1.y,W2.y);                            \
        ffma2(A22,V2.x,W2.x); ffma2(A22,V2.y,W2.y);                            \
        ffma2(A23,V3.x,W2.x); ffma2(A23,V3.y,W2.y);                            \
        ffma2(A30,V0.x,W3.x); ffma2(A30,V0.y,W3.y);                            \
        ffma2(A31,V1.x,W3.x); ffma2(A31,V1.y,W3.y);                            \
        ffma2(A32,V2.x,W3.x); ffma2(A32,V2.y,W3.y);                            \
        ffma2(A33,V3.x,W3.x); ffma2(A33,V3.y,W3.y);                            \
    }

    // reset accumulators + (slice 3 only) x-part for buffer `buf`
    auto do_xpart = [&](int buf) {
        A00=A01=A02=A03=A10=A11=A12=A13=0ull;
        A20=A21=A22=A23=A30=A31=A32=A33=0ull;
        if (ks == 3) {
            #pragma unroll
            for (int q = 0; q < 7; ++q) GEMM_QUAD(s.wih, s.xs[buf], q);
        }
    };

    do_xpart(0);   // x-part for t=0 (xs[0] staged above, synced)

    for (int t = 0; t < T_STEPS; ++t) {
        // prefetch x(t+1): DRAM latency overlaps wait + staging + GEMM
        float xreg = 0.0f;
        if (t + 1 < T_STEPS && xp_on && xp_k < IN_DIM)
            xreg = __ldg(&x[((size_t)(b0 + xp_bl) * T_STEPS + (t + 1)) * IN_DIM + xp_k]);

        if (t > 0) {
            // ---- wait for peers' h(t-1) ----
            if (tid == 0) {
                unsigned v;
                do { v = ld_acq(ep); } while (v == seen);
                seen = v;
            }
            __syncthreads();   // tid0's acquire ordered before everyone's reads

            // ---- stage this slice's h quads; sync within the slice only ----
            {
                const float* hb = &g_h[t & 1][b0][0];
                if (ks < 3) {
                    for (int i = p; i < TB * 14; i += 128) {
                        int bl = i / 14, kq = kq_lo + (i - bl * 14);
                        float4 v = __ldcg(reinterpret_cast<const float4*>(
                                              hb + (size_t)bl * HDIM + 4 * kq));
                        *reinterpret_cast<float4*>(&s.hs[bl][4 * kq]) = v;
                    }
                } else {
                    int bl = p >> 3, kq = 42 + (p & 7);   // 128 items exactly
                    float4 v = __ldcg(reinterpret_cast<const float4*>(
                                          hb + (size_t)bl * HDIM + 4 * kq));
                    *reinterpret_cast<float4*>(&s.hs[bl][4 * kq]) = v;
                }
                bar_named128(8 + ks);
            }

            // ---- recurrent GEMM: fully unrolled, compile-time trip counts ----
            if (ks < 3) {
                #pragma unroll
                for (int i = 0; i < 14; ++i) GEMM_QUAD(s.whh, s.hs, kq_lo + i);
            } else {
                #pragma unroll
                for (int i = 0; i < 8; ++i) GEMM_QUAD(s.whh, s.hs, 42 + i);
            }
        }

        // ---- K-split-4 reduction: slices 1..3 export (real rows only) ----
        if (ks != 0 && act) {
            float (*rd)[RED_S] = s.red[ks - 1];
            rd[r0g][bb]      = f2sum(A00); rd[r0g][bb + 4]  = f2sum(A01);
            rd[r0g][bb + 8]  = f2sum(A02); rd[r0g][bb + 12] = f2sum(A03);
            rd[r1g][bb]      = f2sum(A10); rd[r1g][bb + 4]  = f2sum(A11);
            rd[r1g][bb + 8]  = f2sum(A12); rd[r1g][bb + 12] = f2sum(A13);
            rd[r2g][bb]      = f2sum(A20); rd[r2g][bb + 4]  = f2sum(A21);
            rd[r2g][bb + 8]  = f2sum(A22); rd[r2g][bb + 12] = f2sum(A23);
            rd[r3g][bb]      = f2sum(A30); rd[r3g][bb + 4]  = f2sum(A31);
            rd[r3g][bb + 8]  = f2sum(A32); rd[r3g][bb + 12] = f2sum(A33);
        }
        __syncthreads();

        // ---- fused gather + activations + cell update (ks0, register c) ----
        const int nxt = (t + 1) & 1;
        if (ks == 0 && act) {
            #define CELL(N, AI, AF, AG, AO, CREG)                              \
            {                                                                  \
                int b = bb + 4 * (N);                                          \
                float vi = f2sum(AI) + s.red[0][r0g][b] + s.red[1][r0g][b]     \
                         + s.red[2][r0g][b] + bsi;                             \
                float vf = f2sum(AF) + s.red[0][r1g][b] + s.red[1][r1g][b]     \
                         + s.red[2][r1g][b] + bsf;                             \
                float vg = f2sum(AG) + s.red[0][r2g][b] + s.red[1][r2g][b]     \
                         + s.red[2][r2g][b] + bsg;                             \
                float vo = f2sum(AO) + s.red[0][r3g][b] + s.red[1][r3g][b]     \
                         + s.red[2][r3g][b] + bso;                             \
                float gi = sigf(vi), gf = sigf(vf);                            \
                float gg = tanh_fast(vg), go = sigf(vo);                       \
                CREG = gf * CREG + gi * gg;                                    \
                __stcg(&g_h[nxt][b0 + b][hd0 + jb], go * tanh_fast(CREG));     \
            }
            CELL(0, A00, A10, A20, A30, creg0)
            CELL(1, A01, A11, A21, A31, creg1)
            CELL(2, A02, A12, A22, A32, creg2)
            CELL(3, A03, A13, A23, A33, creg3)
            #undef CELL
        }
        if (t + 1 < T_STEPS && xp_on)
            s.xs[nxt][xp_bl][xp_k] = xreg;

        __syncthreads();   // covers stcg (for arrive-release), xs STS, red reuse

        if (tid == 0) {
            unsigned old = atom_add_acqrel(cnt, 1u);
            if (old == GSIZE - 1) {
                atomicExch(cnt, 0u);
                atom_add_acqrel(ep, 1u);      // flip
            }
        }

        // ---- x-part for t+1 (slice 3; hidden under peer skew) ----
        if (t + 1 < T_STEPS) do_xpart(nxt);
    }

    // ---- final wait: peers' h(2047) (stored in g_h[0]) visible ----
    if (tid == 0) {
        unsigned v;
        do { v = ld_acq(ep); } while (v == seen);
        seen = v;
    }
    __syncthreads();
    {
        const float4* hsrc = reinterpret_cast<const float4*>(&g_h[0][b0][0]);
        for (int i = tid; i < TB * (HDIM / 4); i += NTHREADS) {
            int bl = i / 50, kq = i - bl * 50;
            float4 v = __ldcg(hsrc + i);
            *reinterpret_cast<float4*>(&s.hs[bl][kq * 4]) = v;
        }
    }
    __syncthreads();

    // outputs: [out(512) | h(51200) | c(51200)]
    if (ht == 0 && out_size >= NCLS * BATCH) {
        if (tid < TB * NCLS) {
            int bl = tid >> 1, cls = tid & 1;
            float acc = fc_b[cls];
            #pragma unroll 4
            for (int k = 0; k < HDIM; ++k)
                acc += s.hs[bl][k] * fc_w[cls * HDIM + k];
            out[(b0 + bl) * NCLS + cls] = sigf(acc);
        }
    }
    if (ht == 0 && out_size >= NCLS * BATCH + BATCH * HDIM) {
        for (int i = tid; i < TB * HDIM; i += NTHREADS) {
            int bl = i / HDIM, k = i - bl * HDIM;
            out[NCLS * BATCH + (size_t)(b0 + bl) * HDIM + k] = s.hs[bl][k];
        }
    }
    if (out_size >= NCLS * BATCH + 2 * BATCH * HDIM) {
        if (ks == 0 && act) {   // c lives in ks0 registers
            #pragma unroll
            for (int n = 0; n < 4; ++n) {
                int b = bb + 4 * n;
                float cv = (n == 0) ? creg0 : (n == 1) ? creg1
                                            : (n == 2) ? creg2 : creg3;
                out[NCLS * BATCH + BATCH * HDIM
                    + (size_t)(b0 + b) * HDIM + hd0 + jb] = cv;
            }
        }
    }
}

extern "C" void kernel_launch(void* const* d_in, const int* in_sizes, int n_in,
                              void* d_out, int out_size) {
    const float* x     = (const float*)d_in[0];
    // d_in[1]=X_lengths (unused), d_in[2]=h0, d_in[3]=c0 (zeros, ignored)
    const float* W_ih  = (const float*)d_in[4];
    const float* W_hh  = (const float*)d_in[5];
    const float* b_ih  = (const float*)d_in[6];
    const float* b_hh  = (const float*)d_in[7];
    const float* fc_w  = (const float*)d_in[8];
    const float* fc_b  = (const float*)d_in[9];

    int smem = (int)sizeof(SmemLayout);
    cudaFuncSetAttribute(lstm_persistent,
                         cudaFuncAttributeMaxDynamicSharedMemorySize, smem);
    lstm_persistent<<<GRID_CTAS, NTHREADS, smem>>>(
        x, W_ih, W_hh, b_ih, b_hh, fc_w, fc_b, (float*)d_out, out_size);
}